// round 1
// baseline (speedup 1.0000x reference)
#include <cuda_runtime.h>

typedef unsigned long long u64;

__device__ __forceinline__ u64 ffma2(u64 a, u64 b, u64 c){
    u64 d;
    asm("fma.rn.f32x2 %0, %1, %2, %3;" : "=l"(d) : "l"(a), "l"(b), "l"(c));
    return d;
}
__device__ __forceinline__ u64 pack2(float x){
    u64 r;
    asm("mov.b64 %0, {%1, %1};" : "=l"(r) : "f"(x));
    return r;
}
__device__ __forceinline__ float2 unpack2(u64 v){
    float lo, hi;
    asm("mov.b64 {%0, %1}, %2;" : "=f"(lo), "=f"(hi) : "l"(v));
    return make_float2(lo, hi);
}

// h[0..31] are packed f32x2 accumulators covering 64 outputs.
// wrow: 64 contiguous floats in smem (16B aligned). a: broadcast activation.
__device__ __forceinline__ void accrow(u64* __restrict__ h, const float* __restrict__ wrow, float a){
    u64 a2 = pack2(a);
    const ulonglong2* w = (const ulonglong2*)wrow;
    #pragma unroll
    for (int j = 0; j < 16; j++){
        ulonglong2 t = w[j];
        h[2*j]   = ffma2(a2, t.x, h[2*j]);
        h[2*j+1] = ffma2(a2, t.y, h[2*j+1]);
    }
}

// ---- shared memory layout (in floats) ----
#define SM_W1 0            // 39*64 = 2496
#define SM_B1 2496         // 64
#define SM_W2 2560         // 64*64 = 4096
#define SM_B2 6656         // 64
#define SM_WD 6720         // 64 packed float2 (W3 col diffs) = 128
#define SM_C  6848         // 2  (b3 diffs)
#define SM_X  6852         // 128 * 140  (x staging)  -- 16B aligned (6852*4 % 16 == 0)
#define BPB   128
#define SMEM_FLOATS (SM_X + BPB*140)

__global__ __launch_bounds__(BPB) void maddpg_kernel(
    const float* __restrict__ x,
    const float* __restrict__ W1, const float* __restrict__ b1,
    const float* __restrict__ W2, const float* __restrict__ b2,
    const float* __restrict__ W3, const float* __restrict__ b3,
    const int* __restrict__ idx,
    float* __restrict__ out, int B)
{
    extern __shared__ float sm[];
    __shared__ int sIdx[8];
    const int tid = threadIdx.x;
    const int b0  = blockIdx.x * BPB;

    // ---- load weights into smem (vectorized; all arrays 16B aligned from cudaMalloc) ----
    {
        float4* s4 = (float4*)(sm + SM_W1);
        const float4* g4 = (const float4*)W1;
        #pragma unroll 2
        for (int i = tid; i < 624; i += BPB) s4[i] = g4[i];
    }
    if (tid < 16)  ((float4*)(sm + SM_B1))[tid] = ((const float4*)b1)[tid];
    {
        float4* s4 = (float4*)(sm + SM_W2);
        const float4* g4 = (const float4*)W2;
        #pragma unroll 2
        for (int i = tid; i < 1024; i += BPB) s4[i] = g4[i];
    }
    if (tid < 16)  ((float4*)(sm + SM_B2))[tid] = ((const float4*)b2)[tid];
    if (tid < 64){
        // only r[1]-r[2] and r[3]-r[4] survive to the output: fold W3 columns now
        float a1 = W3[tid*5+1], a2 = W3[tid*5+2], a3 = W3[tid*5+3], a4 = W3[tid*5+4];
        sm[SM_WD + 2*tid]     = a1 - a2;
        sm[SM_WD + 2*tid + 1] = a3 - a4;
    }
    if (tid == 0){ sm[SM_C] = b3[1]-b3[2]; sm[SM_C+1] = b3[3]-b3[4]; }
    if (tid < 8) sIdx[tid] = idx[tid];

    // ---- stage this block's x slab: 128 batches * 140 floats, fully coalesced ----
    {
        float4* sx4 = (float4*)(sm + SM_X);
        const float4* gx4 = (const float4*)x;
        long gbase = (long)b0 * 35;
        long gtot  = (long)B * 35;
        #pragma unroll 5
        for (int i = tid; i < BPB*35; i += BPB){
            long gi = gbase + i;
            if (gi < gtot) sx4[i] = gx4[gi];
        }
    }
    __syncthreads();

    const int b = b0 + tid;
    if (b >= B) return;

    const float* xb = sm + SM_X + tid*140;
    const float p0 = xb[0], p1 = xb[1];

    // ================= layer 1: h = b1 + sum_k obs[k] * W1[k,:] =================
    u64 h[32];
    {
        const u64* bb = (const u64*)(sm + SM_B1);
        #pragma unroll
        for (int j = 0; j < 32; j++) h[j] = bb[j];
    }
    const float* sW1p = sm + SM_W1;

    // o_self: obs[0..4] = x[b,0,0:5]
    accrow(h, sW1p + 0*64, xb[0]);
    accrow(h, sW1p + 1*64, xb[1]);
    accrow(h, sW1p + 2*64, xb[2]);
    accrow(h, sW1p + 3*64, xb[3]);
    accrow(h, sW1p + 4*64, xb[4]);

    // mid: rel = x[b,i,5:7] + x[b,i,0:2] - pos  (third column is structurally 0 -> skipped)
    #pragma unroll
    for (int m = 0; m < 3; m++){
        const float* r = xb + sIdx[m]*7;
        float rx = (r[5] + r[0]) - p0;
        float ry = (r[6] + r[1]) - p1;
        accrow(h, sW1p + (5+3*m)*64, rx);
        accrow(h, sW1p + (6+3*m)*64, ry);
    }

    // obst: masked by dist < RADIUS; skipping when masked-out is exact (adds 0*w)
    #pragma unroll
    for (int m = 0; m < 5; m++){
        const float* r = xb + (sIdx[3+m] + 10)*7;
        float dx = r[0] - p0, dy = r[1] - p1;
        if (dx*dx + dy*dy < 0.0225f){   // 0.15^2 ; sqrt is monotone
            const float* w = sW1p + (14+5*m)*64;
            accrow(h, w,        dx);
            accrow(h, w + 64,   dy);
            accrow(h, w + 128, r[2]);
            accrow(h, w + 192, r[3]);
            accrow(h, w + 256, r[4]);
        }
    }

    // ================= relu + layer 2 =================
    float h1[64];
    #pragma unroll
    for (int j = 0; j < 32; j++){
        float2 f = unpack2(h[j]);
        h1[2*j]   = fmaxf(f.x, 0.0f);
        h1[2*j+1] = fmaxf(f.y, 0.0f);
    }
    u64 g[32];
    {
        const u64* bb = (const u64*)(sm + SM_B2);
        #pragma unroll
        for (int j = 0; j < 32; j++) g[j] = bb[j];
    }
    const float* sW2p = sm + SM_W2;
    #pragma unroll
    for (int k = 0; k < 64; k++){
        accrow(g, sW2p + k*64, h1[k]);
    }

    // ================= relu + folded layer 3 =================
    u64 acc0 = *(const u64*)(sm + SM_C);
    u64 acc1 = pack2(0.0f);
    const u64* wd = (const u64*)(sm + SM_WD);
    #pragma unroll
    for (int j = 0; j < 32; j++){
        float2 f = unpack2(g[j]);
        acc0 = ffma2(pack2(fmaxf(f.x, 0.0f)), wd[2*j],     acc0);
        acc1 = ffma2(pack2(fmaxf(f.y, 0.0f)), wd[2*j + 1], acc1);
    }
    u64 acc;
    asm("add.rn.f32x2 %0, %1, %2;" : "=l"(acc) : "l"(acc0), "l"(acc1));

    float2 res = unpack2(acc);
    float v0 = res.x * 0.1f;
    float v1 = res.y * 0.1f;
    if (fabsf(v0) > 1.0f) v0 = copysignf(2.0f, v0);
    if (fabsf(v1) > 1.0f) v1 = copysignf(2.0f, v1);
    ((float2*)out)[b] = make_float2(v0, v1);
}

extern "C" void kernel_launch(void* const* d_in, const int* in_sizes, int n_in,
                              void* d_out, int out_size)
{
    const float* x  = (const float*)d_in[0];
    const float* W1 = (const float*)d_in[1];
    const float* b1 = (const float*)d_in[2];
    const float* W2 = (const float*)d_in[3];
    const float* b2 = (const float*)d_in[4];
    const float* W3 = (const float*)d_in[5];
    const float* b3 = (const float*)d_in[6];
    const int*  idx = (const int*)d_in[7];

    const int B = in_sizes[0] / 140;               // x: (B, 20, 7)
    const int blocks = (B + BPB - 1) / BPB;
    const size_t smem = SMEM_FLOATS * sizeof(float);  // ~99 KB -> needs opt-in

    cudaFuncSetAttribute(maddpg_kernel,
                         cudaFuncAttributeMaxDynamicSharedMemorySize, (int)smem);

    maddpg_kernel<<<blocks, BPB, smem>>>(x, W1, b1, W2, b2, W3, b3, idx,
                                         (float*)d_out, B);
}